// round 5
// baseline (speedup 1.0000x reference)
#include <cuda_runtime.h>
#include <math.h>
#include <stdint.h>

// SOMFNN: two layers of (ALMMo codebook lamb) + sigmoid(Linear)
// stau = base/2 (scalar); prototypes are input samples -> all distances from
// Gram = X X^T; min-distance-over-all-predecessors shortcut for new rules.
// GEMMs on tensor cores (tf32 mma.sync, RNA-rounded inputs), 16 warps/CTA.

#define MAXN 2048
#define MAXD 2048
#define NCHUNK 16
#define LDSW 20   // padded floats per smem row (16 data + 4 pad)

__device__ float g_G[(size_t)MAXN * MAXN];
__device__ float g_H[(size_t)MAXN * MAXD];
__device__ float g_SEN[MAXN];
__device__ float g_colpart[NCHUNK][MAXD];
__device__ float g_base[2];
__device__ float g_mind[MAXN];
__device__ int   g_rules[MAXN];
__device__ int   g_protos[MAXN];
__device__ int   g_count[1];

// ---------------- block reductions ----------------
__device__ __forceinline__ float blockReduceSum(float v) {
    __shared__ float sh[32];
    int lane = threadIdx.x & 31, wid = threadIdx.x >> 5;
#pragma unroll
    for (int o = 16; o; o >>= 1) v += __shfl_down_sync(0xffffffffu, v, o);
    __syncthreads();
    if (lane == 0) sh[wid] = v;
    __syncthreads();
    if (wid == 0) {
        int nw = (blockDim.x + 31) >> 5;
        v = (lane < nw) ? sh[lane] : 0.0f;
#pragma unroll
        for (int o = 16; o; o >>= 1) v += __shfl_down_sync(0xffffffffu, v, o);
    }
    return v;
}

__device__ __forceinline__ float blockReduceMin(float v) {
    __shared__ float sh[32];
    int lane = threadIdx.x & 31, wid = threadIdx.x >> 5;
#pragma unroll
    for (int o = 16; o; o >>= 1) v = fminf(v, __shfl_down_sync(0xffffffffu, v, o));
    __syncthreads();
    if (lane == 0) sh[wid] = v;
    __syncthreads();
    if (wid == 0) {
        int nw = (blockDim.x + 31) >> 5;
        v = (lane < nw) ? sh[lane] : INFINITY;
#pragma unroll
        for (int o = 16; o; o >>= 1) v = fminf(v, __shfl_down_sync(0xffffffffu, v, o));
    }
    return v;
}

// ---------------- small prep kernels ----------------
__global__ void rowsumsq_kernel(const float* __restrict__ X, int K) {
    int i = blockIdx.x;
    const float4* row = (const float4*)(X + (size_t)i * K);
    float s = 0.0f;
    for (int k = threadIdx.x; k < (K >> 2); k += blockDim.x) {
        float4 v = row[k];
        s += v.x * v.x + v.y * v.y + v.z * v.z + v.w * v.w;
    }
    s = blockReduceSum(s);
    if (threadIdx.x == 0) g_SEN[i] = s;
}

__global__ void colsum_kernel(const float* __restrict__ X, int N, int K) {
    int c = blockIdx.x * blockDim.x + threadIdx.x;
    int chunk = blockIdx.y;
    if (c >= K) return;
    int r0 = chunk * (N / NCHUNK), r1 = r0 + N / NCHUNK;
    float s = 0.0f;
    for (int i = r0; i < r1; i++) s += X[(size_t)i * K + c];
    g_colpart[chunk][c] = s;
}

__global__ void base_kernel(int N, int K) {
    float invN = 1.0f / (float)N;
    float s1 = 0.0f, s2 = 0.0f;
    for (int i = threadIdx.x; i < N; i += blockDim.x) s1 += g_SEN[i];
    for (int c = threadIdx.x; c < K; c += blockDim.x) {
        float cs = 0.0f;
#pragma unroll
        for (int h = 0; h < NCHUNK; h++) cs += g_colpart[h][c];
        float m = cs * invN;
        s2 += m * m;
    }
    s1 = blockReduceSum(s1);
    __syncthreads();
    s2 = blockReduceSum(s2);
    if (threadIdx.x == 0) {
        float base = s1 * invN - s2;
        g_base[0] = base;
        g_base[1] = 0.5f * base;
    }
}

// ---------------- tensor-core helpers ----------------
__device__ __forceinline__ unsigned f2tf(float f) {
    unsigned u;
    asm("cvt.rna.tf32.f32 %0, %1;" : "=r"(u) : "f"(f));
    return u;
}

__device__ __forceinline__ unsigned smaddr(const void* p) {
    unsigned r;
    asm("{.reg .u64 t; cvta.to.shared.u64 t, %1; cvt.u32.u64 %0, t;}"
        : "=r"(r) : "l"(p));
    return r;
}

__device__ __forceinline__ void ldsm4(unsigned& r0, unsigned& r1, unsigned& r2,
                                      unsigned& r3, unsigned a) {
    asm volatile("ldmatrix.sync.aligned.m8n8.x4.shared.b16 {%0,%1,%2,%3},[%4];"
                 : "=r"(r0), "=r"(r1), "=r"(r2), "=r"(r3) : "r"(a));
}

__device__ __forceinline__ void mma_tf32(float* c, const unsigned* a, const unsigned* b) {
    asm volatile(
        "mma.sync.aligned.m16n8k8.row.col.f32.tf32.tf32.f32 "
        "{%0,%1,%2,%3},{%4,%5,%6,%7},{%8,%9},{%0,%1,%2,%3};"
        : "+f"(c[0]), "+f"(c[1]), "+f"(c[2]), "+f"(c[3])
        : "r"(a[0]), "r"(a[1]), "r"(a[2]), "r"(a[3]), "r"(b[0]), "r"(b[1]));
}

// ---------------- tf32 tensor-core GEMM (NT), 512 threads -------------------
// C[i,j] = sum_k A[i,k]*B[j,k]. mode 0: plain, 1: bias+sigmoid, 2: symmetric
// Gram (A==B, triangular 1D grid, mirrored store). M,N mult 128, K mult 16.
// 16 warps in a 4(m) x 4(n) grid; warp tile 32x32.
__global__ void __launch_bounds__(512, 1)
gemm_tc_kernel(const float* __restrict__ A, const float* __restrict__ B,
               float* __restrict__ C, int M, int N, int K,
               const float* __restrict__ bias, int mode) {
    __shared__ unsigned As[2][128 * LDSW];
    __shared__ unsigned Bs[2][128 * LDSW];
    const int tid = threadIdx.x;
    const int wid = tid >> 5, lane = tid & 31;

    int bi, bj;
    if (mode == 2) {
        int id = blockIdx.x;
        bi = (int)((sqrtf(8.0f * (float)id + 1.0f) - 1.0f) * 0.5f);
        while ((bi + 1) * (bi + 2) / 2 <= id) bi++;
        while (bi * (bi + 1) / 2 > id) bi--;
        bj = id - bi * (bi + 1) / 2;
    } else {
        bi = blockIdx.y; bj = blockIdx.x;
    }
    const int rowBase = bi << 7, colBase = bj << 7;

    // global loads: each thread 1 float4 from A, 1 from B per K-tile
    const int lrow = tid >> 2;        // 0..127
    const int lc4  = tid & 3;         // float4 slot within 16-float row chunk
    const float* Ap = A + (size_t)(rowBase + lrow) * K + lc4 * 4;
    const float* Bp = B + (size_t)(colBase + lrow) * K + lc4 * 4;
    const int sA = lrow * LDSW + lc4 * 4;

    // warp tiling: 4(m) x 4(n), warp tile 32x32
    const int wm = (wid & 3) * 32, wn = (wid >> 2) * 32;
    const int aRow = wm + (lane & 15);
    const int aKof = (lane >> 4) * 4;
    const int bRow = wn + ((lane >> 4) & 1) * 8 + (lane & 7);
    const int bKof = ((lane >> 3) & 1) * 4;

    const unsigned aBase = smaddr(&As[0][0]);
    const unsigned bBase = smaddr(&Bs[0][0]);
    const unsigned bufStride = 128 * LDSW * 4;

    float acc[2][4][4];
#pragma unroll
    for (int fm = 0; fm < 2; fm++)
#pragma unroll
        for (int fn = 0; fn < 4; fn++)
#pragma unroll
            for (int q = 0; q < 4; q++) acc[fm][fn][q] = 0.0f;

    // preload tile 0
    float4 fa = *(const float4*)Ap;
    float4 fb = *(const float4*)Bp;
    {
        unsigned* da = &As[0][0]; unsigned* db = &Bs[0][0];
        da[sA] = f2tf(fa.x); da[sA+1] = f2tf(fa.y); da[sA+2] = f2tf(fa.z); da[sA+3] = f2tf(fa.w);
        db[sA] = f2tf(fb.x); db[sA+1] = f2tf(fb.y); db[sA+2] = f2tf(fb.z); db[sA+3] = f2tf(fb.w);
    }
    __syncthreads();

    const int nt = K >> 4;
    int buf = 0;
    for (int t = 0; t < nt; t++) {
        if (t + 1 < nt) {
            fa = *(const float4*)(Ap + (size_t)(t + 1) * 16);
            fb = *(const float4*)(Bp + (size_t)(t + 1) * 16);
        }
        const unsigned aB = aBase + buf * bufStride;
        const unsigned bB = bBase + buf * bufStride;
#pragma unroll
        for (int kg = 0; kg < 2; kg++) {
            unsigned afr[2][4];
#pragma unroll
            for (int fm = 0; fm < 2; fm++) {
                unsigned ad = aB + (unsigned)(((aRow + fm * 16) * LDSW + kg * 8 + aKof) * 4);
                ldsm4(afr[fm][0], afr[fm][1], afr[fm][2], afr[fm][3], ad);
            }
            unsigned bfr[4][2];
#pragma unroll
            for (int fp = 0; fp < 2; fp++) {
                unsigned bd = bB + (unsigned)(((bRow + fp * 16) * LDSW + kg * 8 + bKof) * 4);
                ldsm4(bfr[2*fp][0], bfr[2*fp][1], bfr[2*fp+1][0], bfr[2*fp+1][1], bd);
            }
#pragma unroll
            for (int fm = 0; fm < 2; fm++)
#pragma unroll
                for (int fn = 0; fn < 4; fn++)
                    mma_tf32(acc[fm][fn], afr[fm], bfr[fn]);
        }
        if (t + 1 < nt) {
            int nb = buf ^ 1;
            unsigned* da = &As[nb][0]; unsigned* db = &Bs[nb][0];
            da[sA] = f2tf(fa.x); da[sA+1] = f2tf(fa.y); da[sA+2] = f2tf(fa.z); da[sA+3] = f2tf(fa.w);
            db[sA] = f2tf(fb.x); db[sA+1] = f2tf(fb.y); db[sA+2] = f2tf(fb.z); db[sA+3] = f2tf(fb.w);
            __syncthreads();
            buf = nb;
        }
    }

    // epilogue: c0,c1 at (row, 2c..2c+1), c2,c3 at (row+8, same cols)
    const int crow = lane >> 2;
    const int ccol = (lane & 3) * 2;
    if (mode == 1) {
#pragma unroll
        for (int fm = 0; fm < 2; fm++) {
            int rr = rowBase + wm + fm * 16 + crow;
#pragma unroll
            for (int fn = 0; fn < 4; fn++) {
                int cc = colBase + wn + fn * 8 + ccol;
                float b0v = bias[cc], b1v = bias[cc + 1];
                float2 v;
                v.x = 1.0f / (1.0f + expf(-(acc[fm][fn][0] + b0v)));
                v.y = 1.0f / (1.0f + expf(-(acc[fm][fn][1] + b1v)));
                *(float2*)&C[(size_t)rr * N + cc] = v;
                v.x = 1.0f / (1.0f + expf(-(acc[fm][fn][2] + b0v)));
                v.y = 1.0f / (1.0f + expf(-(acc[fm][fn][3] + b1v)));
                *(float2*)&C[(size_t)(rr + 8) * N + cc] = v;
            }
        }
    } else {
#pragma unroll
        for (int fm = 0; fm < 2; fm++) {
            int rr = rowBase + wm + fm * 16 + crow;
#pragma unroll
            for (int fn = 0; fn < 4; fn++) {
                int cc = colBase + wn + fn * 8 + ccol;
                float2 v0 = make_float2(acc[fm][fn][0], acc[fm][fn][1]);
                float2 v1 = make_float2(acc[fm][fn][2], acc[fm][fn][3]);
                *(float2*)&C[(size_t)rr * N + cc] = v0;
                *(float2*)&C[(size_t)(rr + 8) * N + cc] = v1;
            }
        }
        if (mode == 2 && bi != bj) {
#pragma unroll
            for (int fm = 0; fm < 2; fm++) {
                int rr = rowBase + wm + fm * 16 + crow;
#pragma unroll
                for (int fn = 0; fn < 4; fn++) {
                    int cc = colBase + wn + fn * 8 + ccol;
                    C[(size_t)cc * N + rr]           = acc[fm][fn][0];
                    C[(size_t)(cc + 1) * N + rr]     = acc[fm][fn][1];
                    C[(size_t)cc * N + rr + 8]       = acc[fm][fn][2];
                    C[(size_t)(cc + 1) * N + rr + 8] = acc[fm][fn][3];
                }
            }
        }
    }
}

// ---------------- prefix row-min: min_{j<i} D[i,j] ----------------
__global__ void prefixmin_kernel(int N) {
    int i = blockIdx.x;
    float si = g_SEN[i];
    const float* Gi = g_G + (size_t)i * N;
    float m = INFINITY;
    for (int j = threadIdx.x; j < i; j += blockDim.x) {
        float d = si + g_SEN[j] - 2.0f * Gi[j];
        m = fminf(m, d);
    }
    m = blockReduceMin(m);
    if (threadIdx.x == 0) g_mind[i] = m;
}

// ---------------- sequential rule-creation scan (1 warp, ballot fast path) --
__global__ void scan_kernel(int N) {
    const int lane = threadIdx.x;
    const float DELTA = 0.13533528323661270f;  // exp(-2)
    float stau = g_base[1];
    bool st_ok = (stau > 0.0f) && (stau < 3.0e38f);
    int count = 0;

    for (int i0 = 0; i0 < N; i0 += 32) {
        int lim = (N - i0 < 32) ? (N - i0) : 32;
        int myi = i0 + lane;
        bool cert = false;
        if (myi < N && st_ok) cert = (expf(-g_mind[myi] / stau) < DELTA);
        unsigned mask = __ballot_sync(0xffffffffu, cert);
        unsigned need = (lim == 32) ? 0xffffffffu : ((1u << lim) - 1u);
        if ((mask & need) == need) {
            if (lane < lim) {
                g_rules[myi] = count + lane;
                g_protos[count + lane] = myi;
            }
            count += lim;
            continue;
        }
        for (int t = 0; t < lim; t++) {
            int i = i0 + t;
            bool newr;
            int slot = 0;
            if (count == 0 || ((mask >> t) & 1u)) {
                newr = true;
            } else {
                float si = g_SEN[i];
                const float* Gi = g_G + (size_t)i * N;
                float best = -INFINITY;
                int bestr = 0x7fffffff;
                for (int r = lane; r < count; r += 32) {
                    int pr = g_protos[r];
                    float d = si + g_SEN[pr] - 2.0f * Gi[pr];
                    float dens = expf(-d / stau);
                    if (dens > best) { best = dens; bestr = r; }
                }
#pragma unroll
                for (int off = 16; off; off >>= 1) {
                    float ob = __shfl_down_sync(0xffffffffu, best, off);
                    int obr = __shfl_down_sync(0xffffffffu, bestr, off);
                    if (ob > best || (ob == best && obr < bestr)) { best = ob; bestr = obr; }
                }
                best  = __shfl_sync(0xffffffffu, best, 0);
                bestr = __shfl_sync(0xffffffffu, bestr, 0);
                newr = (best < DELTA);
                slot = bestr;
            }
            if (newr) slot = count;
            if (lane == 0) g_rules[i] = slot;
            if (newr) {
                if (lane == 0) g_protos[count] = i;
                count++;
            }
        }
    }
    if (lane == 0) g_count[0] = count;
}

// ---------------- final normalized densities ----------------
__global__ void lamb_kernel(int N, float* __restrict__ out) {
    int n = blockIdx.x;
    int count = g_count[0];
    float stau = g_base[1];
    float sn = g_SEN[n];
    const float* Gn = g_G + (size_t)n * N;
    float s = 0.0f;
    for (int r = threadIdx.x; r < count; r += blockDim.x) {
        int pr = g_protos[r];
        float d = sn + g_SEN[pr] - 2.0f * Gn[pr];
        s += expf(-d / stau);
    }
    s = blockReduceSum(s);
    if (threadIdx.x == 0) {
        int pr = g_protos[g_rules[n]];
        float d = sn + g_SEN[pr] - 2.0f * Gn[pr];
        out[n] = expf(-d / stau) / s;
    }
}

// ---------------- host-side orchestration ----------------
static void run_codebook(const float* X, int N, int K, float* lamb_out, float* Gptr) {
    rowsumsq_kernel<<<N, 256>>>(X, K);
    dim3 cg((K + 255) / 256, NCHUNK);
    colsum_kernel<<<cg, 256>>>(X, N, K);
    base_kernel<<<1, 256>>>(N, K);
    int G = N / 128;
    int tri = G * (G + 1) / 2;
    gemm_tc_kernel<<<tri, 512>>>(X, X, Gptr, N, N, K, nullptr, 2);
    prefixmin_kernel<<<N, 256>>>(N);
    scan_kernel<<<1, 32>>>(N);
    lamb_kernel<<<N, 256>>>(N, lamb_out);
}

extern "C" void kernel_launch(void* const* d_in, const int* in_sizes, int n_in,
                              void* d_out, int out_size) {
    const float* x  = (const float*)d_in[0];
    const float* W0 = (const float*)d_in[1];
    const float* b0 = (const float*)d_in[2];
    const float* W1 = (const float*)d_in[3];
    const float* b1 = (const float*)d_in[4];

    int DH   = in_sizes[2];            // 2048
    int DOUT = in_sizes[4];            // 1024
    int DIN  = in_sizes[1] / DH;       // 2048
    int N    = in_sizes[0] / DIN;      // 2048

    float* out   = (float*)d_out;
    float* outH  = out;                          // h: [N, DOUT]
    float* lamb0 = out + (size_t)N * DOUT;       // lambs[0]
    float* lamb1 = lamb0 + N;                    // lambs[1]

    float* Gptr = nullptr;
    float* Hptr = nullptr;
    cudaGetSymbolAddress((void**)&Gptr, g_G);
    cudaGetSymbolAddress((void**)&Hptr, g_H);

    // ---- layer 0 ----
    run_codebook(x, N, DIN, lamb0, Gptr);
    {
        dim3 g0(DH / 128, N / 128);
        gemm_tc_kernel<<<g0, 512>>>(x, W0, Hptr, N, DH, DIN, b0, 1);
    }

    // ---- layer 1 ----
    run_codebook(Hptr, N, DH, lamb1, Gptr);
    {
        dim3 g1(DOUT / 128, N / 128);
        gemm_tc_kernel<<<g1, 512>>>(Hptr, W1, outH, N, DOUT, DH, b1, 1);
    }
}

// round 6
// speedup vs baseline: 1.5284x; 1.5284x over previous
#include <cuda_runtime.h>
#include <cuda_fp16.h>
#include <math.h>
#include <stdint.h>

// SOMFNN: two layers of (ALMMo codebook lamb) + sigmoid(Linear)
// stau = base/2 (scalar); prototypes are input samples -> all distances from
// Gram = X X^T; min-distance-over-all-predecessors shortcut for new rules.
// GEMMs: fp16 mma.sync.m16n8k16 (fp32 accum), SW128-swizzled smem,
// operands pre-converted to fp16 once per matrix.

#define MAXN 2048
#define MAXD 2048
#define NCHUNK 16
#define GEMM_SMEM 65536

__device__ float g_G[(size_t)MAXN * MAXN];
__device__ float g_H[(size_t)MAXN * MAXD];
__device__ __half g_Ah[(size_t)MAXN * MAXD];
__device__ __half g_Bh[(size_t)MAXN * MAXD];
__device__ float g_SEN[MAXN];
__device__ float g_colpart[NCHUNK][MAXD];
__device__ float g_base[2];
__device__ float g_mind[MAXN];
__device__ int   g_rules[MAXN];
__device__ int   g_protos[MAXN];
__device__ int   g_count[1];

// ---------------- block reductions ----------------
__device__ __forceinline__ float blockReduceSum(float v) {
    __shared__ float sh[32];
    int lane = threadIdx.x & 31, wid = threadIdx.x >> 5;
#pragma unroll
    for (int o = 16; o; o >>= 1) v += __shfl_down_sync(0xffffffffu, v, o);
    __syncthreads();
    if (lane == 0) sh[wid] = v;
    __syncthreads();
    if (wid == 0) {
        int nw = (blockDim.x + 31) >> 5;
        v = (lane < nw) ? sh[lane] : 0.0f;
#pragma unroll
        for (int o = 16; o; o >>= 1) v += __shfl_down_sync(0xffffffffu, v, o);
    }
    return v;
}

__device__ __forceinline__ float blockReduceMin(float v) {
    __shared__ float sh[32];
    int lane = threadIdx.x & 31, wid = threadIdx.x >> 5;
#pragma unroll
    for (int o = 16; o; o >>= 1) v = fminf(v, __shfl_down_sync(0xffffffffu, v, o));
    __syncthreads();
    if (lane == 0) sh[wid] = v;
    __syncthreads();
    if (wid == 0) {
        int nw = (blockDim.x + 31) >> 5;
        v = (lane < nw) ? sh[lane] : INFINITY;
#pragma unroll
        for (int o = 16; o; o >>= 1) v = fminf(v, __shfl_down_sync(0xffffffffu, v, o));
    }
    return v;
}

// ---------------- small prep kernels ----------------
__global__ void rowsumsq_kernel(const float* __restrict__ X, int K) {
    int i = blockIdx.x;
    const float4* row = (const float4*)(X + (size_t)i * K);
    float s = 0.0f;
    for (int k = threadIdx.x; k < (K >> 2); k += blockDim.x) {
        float4 v = row[k];
        s += v.x * v.x + v.y * v.y + v.z * v.z + v.w * v.w;
    }
    s = blockReduceSum(s);
    if (threadIdx.x == 0) g_SEN[i] = s;
}

__global__ void colsum_kernel(const float* __restrict__ X, int N, int K) {
    int c = blockIdx.x * blockDim.x + threadIdx.x;
    int chunk = blockIdx.y;
    if (c >= K) return;
    int r0 = chunk * (N / NCHUNK), r1 = r0 + N / NCHUNK;
    float s = 0.0f;
    for (int i = r0; i < r1; i++) s += X[(size_t)i * K + c];
    g_colpart[chunk][c] = s;
}

__global__ void base_kernel(int N, int K) {
    float invN = 1.0f / (float)N;
    float s1 = 0.0f, s2 = 0.0f;
    for (int i = threadIdx.x; i < N; i += blockDim.x) s1 += g_SEN[i];
    for (int c = threadIdx.x; c < K; c += blockDim.x) {
        float cs = 0.0f;
#pragma unroll
        for (int h = 0; h < NCHUNK; h++) cs += g_colpart[h][c];
        float m = cs * invN;
        s2 += m * m;
    }
    s1 = blockReduceSum(s1);
    __syncthreads();
    s2 = blockReduceSum(s2);
    if (threadIdx.x == 0) {
        float base = s1 * invN - s2;
        g_base[0] = base;
        g_base[1] = 0.5f * base;
    }
}

// ---------------- fp32 -> fp16 conversion (once per matrix) ----------------
__global__ void f32tof16_kernel(const float* __restrict__ src,
                                __half* __restrict__ dst, int n4) {
    int i = blockIdx.x * blockDim.x + threadIdx.x;
    if (i >= n4) return;
    float4 v = ((const float4*)src)[i];
    __half2* d = (__half2*)dst + 2 * i;
    d[0] = __floats2half2_rn(v.x, v.y);
    d[1] = __floats2half2_rn(v.z, v.w);
}

// ---------------- tensor-core helpers ----------------
__device__ __forceinline__ unsigned smaddr(const void* p) {
    unsigned r;
    asm("{.reg .u64 t; cvta.to.shared.u64 t, %1; cvt.u32.u64 %0, t;}"
        : "=r"(r) : "l"(p));
    return r;
}

__device__ __forceinline__ void ldsm4(unsigned& r0, unsigned& r1, unsigned& r2,
                                      unsigned& r3, unsigned a) {
    asm volatile("ldmatrix.sync.aligned.m8n8.x4.shared.b16 {%0,%1,%2,%3},[%4];"
                 : "=r"(r0), "=r"(r1), "=r"(r2), "=r"(r3) : "r"(a));
}

__device__ __forceinline__ void mma_f16(float* c, const unsigned* a,
                                        unsigned b0, unsigned b1) {
    asm volatile(
        "mma.sync.aligned.m16n8k16.row.col.f32.f16.f16.f32 "
        "{%0,%1,%2,%3},{%4,%5,%6,%7},{%8,%9},{%0,%1,%2,%3};"
        : "+f"(c[0]), "+f"(c[1]), "+f"(c[2]), "+f"(c[3])
        : "r"(a[0]), "r"(a[1]), "r"(a[2]), "r"(a[3]), "r"(b0), "r"(b1));
}

// ---------------- fp16 tensor-core GEMM (NT) --------------------------------
// C[i,j] = sum_k A[i,k]*B[j,k], A/B fp16, C fp32. mode 0: plain,
// 1: bias+sigmoid, 2: symmetric Gram (triangular grid, mirrored store).
// CTA tile 128x128, K-tile 64 (128B rows, SW128 swizzle). 8 warps 4(m)x2(n).
__global__ void __launch_bounds__(256, 2)
gemm_f16_kernel(const __half* __restrict__ A, const __half* __restrict__ B,
                float* __restrict__ C, int M, int N, int K,
                const float* __restrict__ bias, int mode) {
    extern __shared__ char sm[];
    const int tid = threadIdx.x, wid = tid >> 5, lane = tid & 31;

    int bi, bj;
    if (mode == 2) {
        int id = blockIdx.x;
        bi = (int)((sqrtf(8.0f * (float)id + 1.0f) - 1.0f) * 0.5f);
        while ((bi + 1) * (bi + 2) / 2 <= id) bi++;
        while (bi * (bi + 1) / 2 > id) bi--;
        bj = id - bi * (bi + 1) / 2;
    } else {
        bi = blockIdx.y; bj = blockIdx.x;
    }
    const int rowBase = bi << 7, colBase = bj << 7;

    // LDG/STS geometry: thread handles row r, 4 16B chunks (hh selects half)
    const int r = tid >> 1;
    const int hh = tid & 1;
    const __half* Ag = A + (size_t)(rowBase + r) * K + hh * 32;
    const __half* Bg = B + (size_t)(colBase + r) * K + hh * 32;
    unsigned stsOff[4];
#pragma unroll
    for (int j = 0; j < 4; j++)
        stsOff[j] = (unsigned)(r * 128 + ((((hh << 2) + j) ^ (r & 7)) << 4));

    // warp tiling: 4(m) x 2(n); warp tile 32x64
    const int wm = (wid & 3) << 5, wn = (wid >> 2) << 6;
    // A ldmatrix lane mapping (x4: m0-7@k0, m8-15@k0, m0-7@k8, m8-15@k8)
    const int aRow = wm + ((lane >> 3) & 1) * 8 + (lane & 7);
    const int aQ = lane >> 4;                 // k8 selector
    // B ldmatrix lane mapping (x4: n0-7@k0, n0-7@k8, n8-15@k0, n8-15@k8)
    const int bRow = wn + (lane >> 4) * 8 + (lane & 7);
    const int bQ = (lane >> 3) & 1;           // k8 selector

    const unsigned smBase = smaddr(sm);

    float acc[2][8][4];
#pragma unroll
    for (int fm = 0; fm < 2; fm++)
#pragma unroll
        for (int fn = 0; fn < 8; fn++)
#pragma unroll
            for (int q = 0; q < 4; q++) acc[fm][fn][q] = 0.0f;

    uint4 la[4], lb[4];
#pragma unroll
    for (int j = 0; j < 4; j++) {
        la[j] = *(const uint4*)(Ag + j * 8);
        lb[j] = *(const uint4*)(Bg + j * 8);
    }
#pragma unroll
    for (int j = 0; j < 4; j++) {
        *(uint4*)(sm + stsOff[j]) = la[j];
        *(uint4*)(sm + 16384 + stsOff[j]) = lb[j];
    }
    __syncthreads();

    const int nt = K >> 6;
    int buf = 0;
    for (int t = 0; t < nt; t++) {
        if (t + 1 < nt) {
#pragma unroll
            for (int j = 0; j < 4; j++) {
                la[j] = *(const uint4*)(Ag + (size_t)(t + 1) * 64 + j * 8);
                lb[j] = *(const uint4*)(Bg + (size_t)(t + 1) * 64 + j * 8);
            }
        }
        const unsigned aT = smBase + buf * 32768;
        const unsigned bT = aT + 16384;
#pragma unroll
        for (int kg = 0; kg < 4; kg++) {
            unsigned afr[2][4];
#pragma unroll
            for (int fm = 0; fm < 2; fm++) {
                int rr = aRow + fm * 16;
                unsigned ad = aT + (unsigned)(rr * 128 +
                               ((((kg << 1) + aQ) ^ (rr & 7)) << 4));
                ldsm4(afr[fm][0], afr[fm][1], afr[fm][2], afr[fm][3], ad);
            }
#pragma unroll
            for (int fp = 0; fp < 4; fp++) {
                int rr = bRow + fp * 16;
                unsigned bd = bT + (unsigned)(rr * 128 +
                               ((((kg << 1) + bQ) ^ (rr & 7)) << 4));
                unsigned b00, b01, b10, b11;
                ldsm4(b00, b01, b10, b11, bd);
                mma_f16(acc[0][2 * fp],     afr[0], b00, b01);
                mma_f16(acc[0][2 * fp + 1], afr[0], b10, b11);
                mma_f16(acc[1][2 * fp],     afr[1], b00, b01);
                mma_f16(acc[1][2 * fp + 1], afr[1], b10, b11);
            }
        }
        if (t + 1 < nt) {
            buf ^= 1;
            char* dA = sm + buf * 32768;
#pragma unroll
            for (int j = 0; j < 4; j++) {
                *(uint4*)(dA + stsOff[j]) = la[j];
                *(uint4*)(dA + 16384 + stsOff[j]) = lb[j];
            }
            __syncthreads();
        }
    }

    // epilogue: c0,c1 at (row, 2c..2c+1), c2,c3 at (row+8, same cols)
    const int crow = lane >> 2;
    const int ccol = (lane & 3) * 2;
    if (mode == 1) {
#pragma unroll
        for (int fm = 0; fm < 2; fm++) {
            int rr = rowBase + wm + fm * 16 + crow;
#pragma unroll
            for (int fn = 0; fn < 8; fn++) {
                int cc = colBase + wn + fn * 8 + ccol;
                float b0v = bias[cc], b1v = bias[cc + 1];
                float2 v;
                v.x = 1.0f / (1.0f + expf(-(acc[fm][fn][0] + b0v)));
                v.y = 1.0f / (1.0f + expf(-(acc[fm][fn][1] + b1v)));
                *(float2*)&C[(size_t)rr * N + cc] = v;
                v.x = 1.0f / (1.0f + expf(-(acc[fm][fn][2] + b0v)));
                v.y = 1.0f / (1.0f + expf(-(acc[fm][fn][3] + b1v)));
                *(float2*)&C[(size_t)(rr + 8) * N + cc] = v;
            }
        }
    } else {
#pragma unroll
        for (int fm = 0; fm < 2; fm++) {
            int rr = rowBase + wm + fm * 16 + crow;
#pragma unroll
            for (int fn = 0; fn < 8; fn++) {
                int cc = colBase + wn + fn * 8 + ccol;
                float2 v0 = make_float2(acc[fm][fn][0], acc[fm][fn][1]);
                float2 v1 = make_float2(acc[fm][fn][2], acc[fm][fn][3]);
                *(float2*)&C[(size_t)rr * N + cc] = v0;
                *(float2*)&C[(size_t)(rr + 8) * N + cc] = v1;
            }
        }
        if (mode == 2 && bi != bj) {
#pragma unroll
            for (int fm = 0; fm < 2; fm++) {
                int rr = rowBase + wm + fm * 16 + crow;
#pragma unroll
                for (int fn = 0; fn < 8; fn++) {
                    int cc = colBase + wn + fn * 8 + ccol;
                    C[(size_t)cc * N + rr]           = acc[fm][fn][0];
                    C[(size_t)(cc + 1) * N + rr]     = acc[fm][fn][1];
                    C[(size_t)cc * N + rr + 8]       = acc[fm][fn][2];
                    C[(size_t)(cc + 1) * N + rr + 8] = acc[fm][fn][3];
                }
            }
        }
    }
}

// ---------------- prefix row-min: min_{j<i} D[i,j] ----------------
__global__ void prefixmin_kernel(int N) {
    int i = blockIdx.x;
    float si = g_SEN[i];
    const float* Gi = g_G + (size_t)i * N;
    float m = INFINITY;
    for (int j = threadIdx.x; j < i; j += blockDim.x) {
        float d = si + g_SEN[j] - 2.0f * Gi[j];
        m = fminf(m, d);
    }
    m = blockReduceMin(m);
    if (threadIdx.x == 0) g_mind[i] = m;
}

// ---------------- sequential rule-creation scan (1 warp, ballot fast path) --
__global__ void scan_kernel(int N) {
    const int lane = threadIdx.x;
    const float DELTA = 0.13533528323661270f;  // exp(-2)
    float stau = g_base[1];
    bool st_ok = (stau > 0.0f) && (stau < 3.0e38f);
    int count = 0;

    for (int i0 = 0; i0 < N; i0 += 32) {
        int lim = (N - i0 < 32) ? (N - i0) : 32;
        int myi = i0 + lane;
        bool cert = false;
        if (myi < N && st_ok) cert = (expf(-g_mind[myi] / stau) < DELTA);
        unsigned mask = __ballot_sync(0xffffffffu, cert);
        unsigned need = (lim == 32) ? 0xffffffffu : ((1u << lim) - 1u);
        if ((mask & need) == need) {
            if (lane < lim) {
                g_rules[myi] = count + lane;
                g_protos[count + lane] = myi;
            }
            count += lim;
            continue;
        }
        for (int t = 0; t < lim; t++) {
            int i = i0 + t;
            bool newr;
            int slot = 0;
            if (count == 0 || ((mask >> t) & 1u)) {
                newr = true;
            } else {
                float si = g_SEN[i];
                const float* Gi = g_G + (size_t)i * N;
                float best = -INFINITY;
                int bestr = 0x7fffffff;
                for (int rr = lane; rr < count; rr += 32) {
                    int pr = g_protos[rr];
                    float dd = si + g_SEN[pr] - 2.0f * Gi[pr];
                    float dens = expf(-dd / stau);
                    if (dens > best) { best = dens; bestr = rr; }
                }
#pragma unroll
                for (int off = 16; off; off >>= 1) {
                    float ob = __shfl_down_sync(0xffffffffu, best, off);
                    int obr = __shfl_down_sync(0xffffffffu, bestr, off);
                    if (ob > best || (ob == best && obr < bestr)) { best = ob; bestr = obr; }
                }
                best  = __shfl_sync(0xffffffffu, best, 0);
                bestr = __shfl_sync(0xffffffffu, bestr, 0);
                newr = (best < DELTA);
                slot = bestr;
            }
            if (newr) slot = count;
            if (lane == 0) g_rules[i] = slot;
            if (newr) {
                if (lane == 0) g_protos[count] = i;
                count++;
            }
        }
    }
    if (lane == 0) g_count[0] = count;
}

// ---------------- final normalized densities ----------------
__global__ void lamb_kernel(int N, float* __restrict__ out) {
    int n = blockIdx.x;
    int count = g_count[0];
    float stau = g_base[1];
    float sn = g_SEN[n];
    const float* Gn = g_G + (size_t)n * N;
    float s = 0.0f;
    for (int r = threadIdx.x; r < count; r += blockDim.x) {
        int pr = g_protos[r];
        float d = sn + g_SEN[pr] - 2.0f * Gn[pr];
        s += expf(-d / stau);
    }
    s = blockReduceSum(s);
    if (threadIdx.x == 0) {
        int pr = g_protos[g_rules[n]];
        float d = sn + g_SEN[pr] - 2.0f * Gn[pr];
        out[n] = expf(-d / stau) / s;
    }
}

// ---------------- host-side orchestration ----------------
static void convert_f16(const float* src, __half* dst, size_t n) {
    int n4 = (int)(n >> 2);
    f32tof16_kernel<<<(n4 + 255) / 256, 256>>>(src, dst, n4);
}

static void run_codebook(const __half* Xh, const float* X, int N, int K,
                         float* lamb_out, float* Gptr) {
    rowsumsq_kernel<<<N, 256>>>(X, K);
    dim3 cg((K + 255) / 256, NCHUNK);
    colsum_kernel<<<cg, 256>>>(X, N, K);
    base_kernel<<<1, 256>>>(N, K);
    int G = N / 128;
    int tri = G * (G + 1) / 2;
    gemm_f16_kernel<<<tri, 256, GEMM_SMEM>>>(Xh, Xh, Gptr, N, N, K, nullptr, 2);
    prefixmin_kernel<<<N, 256>>>(N);
    scan_kernel<<<1, 32>>>(N);
    lamb_kernel<<<N, 256>>>(N, lamb_out);
}

extern "C" void kernel_launch(void* const* d_in, const int* in_sizes, int n_in,
                              void* d_out, int out_size) {
    const float* x  = (const float*)d_in[0];
    const float* W0 = (const float*)d_in[1];
    const float* b0 = (const float*)d_in[2];
    const float* W1 = (const float*)d_in[3];
    const float* b1 = (const float*)d_in[4];

    int DH   = in_sizes[2];            // 2048
    int DOUT = in_sizes[4];            // 1024
    int DIN  = in_sizes[1] / DH;       // 2048
    int N    = in_sizes[0] / DIN;      // 2048

    float* out   = (float*)d_out;
    float* outH  = out;                          // h: [N, DOUT]
    float* lamb0 = out + (size_t)N * DOUT;       // lambs[0]
    float* lamb1 = lamb0 + N;                    // lambs[1]

    float* Gptr = nullptr;
    float* Hptr = nullptr;
    __half* Ah = nullptr;
    __half* Bh = nullptr;
    cudaGetSymbolAddress((void**)&Gptr, g_G);
    cudaGetSymbolAddress((void**)&Hptr, g_H);
    cudaGetSymbolAddress((void**)&Ah, g_Ah);
    cudaGetSymbolAddress((void**)&Bh, g_Bh);

    cudaFuncSetAttribute(gemm_f16_kernel,
                         cudaFuncAttributeMaxDynamicSharedMemorySize, GEMM_SMEM);

    // ---- layer 0 ----
    convert_f16(x, Ah, (size_t)N * DIN);
    run_codebook(Ah, x, N, DIN, lamb0, Gptr);
    convert_f16(W0, Bh, (size_t)DH * DIN);
    {
        dim3 g0(DH / 128, N / 128);
        gemm_f16_kernel<<<g0, 256, GEMM_SMEM>>>(Ah, Bh, Hptr, N, DH, DIN, b0, 1);
    }

    // ---- layer 1 ----
    convert_f16(Hptr, Ah, (size_t)N * DH);
    run_codebook(Ah, Hptr, N, DH, lamb1, Gptr);
    convert_f16(W1, Bh, (size_t)DOUT * DH);
    {
        dim3 g1(DOUT / 128, N / 128);
        gemm_f16_kernel<<<g1, 256, GEMM_SMEM>>>(Ah, Bh, outH, N, DOUT, DH, b1, 1);
    }
}

// round 8
// speedup vs baseline: 1.5640x; 1.0232x over previous
#include <cuda_runtime.h>
#include <cuda_fp16.h>
#include <math.h>
#include <stdint.h>

// SOMFNN: two layers of (ALMMo codebook lamb) + sigmoid(Linear)
// stau = base/2 (scalar); prototypes are input samples -> all distances from
// Gram = X X^T; min-distance-over-all-predecessors shortcut for new rules.
// GEMMs: fp16 mma.sync.m16n8k16 (fp32 accum), SW128-swizzled smem.
// Prefix-min fused into the Gram epilogue via order-preserving atomicMin.
// lin0 writes fp16 H into a SEPARATE buffer (g_Hh) to avoid aliasing its own
// A operand (the r7 bug).

#define MAXN 2048
#define MAXD 2048
#define NCHUNK 32
#define GEMM_SMEM 65536

__device__ float g_G[(size_t)MAXN * MAXN];
__device__ float g_H[(size_t)MAXN * MAXD];
__device__ __half g_Ah[(size_t)MAXN * MAXD];
__device__ __half g_Bh[(size_t)MAXN * MAXD];
__device__ __half g_Hh[(size_t)MAXN * MAXD];
__device__ float g_SEN[MAXN];
__device__ float g_colpart[NCHUNK][MAXD];
__device__ float g_base[2];
__device__ unsigned g_mindu[MAXN];   // encoded min_{j<i} D[i,j]
__device__ int   g_rules[MAXN];
__device__ int   g_protos[MAXN];
__device__ int   g_count[1];

// order-preserving float<->unsigned encoding (monotone; min exact)
__device__ __forceinline__ unsigned encf(float f) {
    unsigned u = __float_as_uint(f);
    return (u & 0x80000000u) ? ~u : (u | 0x80000000u);
}
__device__ __forceinline__ float decf(unsigned e) {
    unsigned u = (e & 0x80000000u) ? (e ^ 0x80000000u) : ~e;
    return __uint_as_float(u);
}

// ---------------- block reductions ----------------
__device__ __forceinline__ float blockReduceSum(float v) {
    __shared__ float sh[32];
    int lane = threadIdx.x & 31, wid = threadIdx.x >> 5;
#pragma unroll
    for (int o = 16; o; o >>= 1) v += __shfl_down_sync(0xffffffffu, v, o);
    __syncthreads();
    if (lane == 0) sh[wid] = v;
    __syncthreads();
    if (wid == 0) {
        int nw = (blockDim.x + 31) >> 5;
        v = (lane < nw) ? sh[lane] : 0.0f;
#pragma unroll
        for (int o = 16; o; o >>= 1) v += __shfl_down_sync(0xffffffffu, v, o);
    }
    return v;
}

// ---------------- small prep kernels ----------------
__global__ void rowsumsq_kernel(const float* __restrict__ X, int K) {
    int i = blockIdx.x;
    const float4* row = (const float4*)(X + (size_t)i * K);
    float s = 0.0f;
    for (int k = threadIdx.x; k < (K >> 2); k += blockDim.x) {
        float4 v = row[k];
        s += v.x * v.x + v.y * v.y + v.z * v.z + v.w * v.w;
    }
    s = blockReduceSum(s);
    if (threadIdx.x == 0) g_SEN[i] = s;
}

__global__ void colsum_kernel(const float* __restrict__ X, int N, int K) {
    int c = blockIdx.x * blockDim.x + threadIdx.x;
    int chunk = blockIdx.y;
    if (c >= K) return;
    int r0 = chunk * (N / NCHUNK), r1 = r0 + N / NCHUNK;
    float s = 0.0f;
    for (int i = r0; i < r1; i++) s += X[(size_t)i * K + c];
    g_colpart[chunk][c] = s;
}

__global__ void base_kernel(int N, int K) {
    float invN = 1.0f / (float)N;
    float s1 = 0.0f, s2 = 0.0f;
    for (int i = threadIdx.x; i < N; i += blockDim.x) s1 += g_SEN[i];
    for (int c = threadIdx.x; c < K; c += blockDim.x) {
        float cs = 0.0f;
#pragma unroll
        for (int h = 0; h < NCHUNK; h++) cs += g_colpart[h][c];
        float m = cs * invN;
        s2 += m * m;
    }
    s1 = blockReduceSum(s1);
    __syncthreads();
    s2 = blockReduceSum(s2);
    if (threadIdx.x == 0) {
        float base = s1 * invN - s2;
        g_base[0] = base;
        g_base[1] = 0.5f * base;
    }
}

__global__ void mindinit_kernel(int N) {
    int i = blockIdx.x * blockDim.x + threadIdx.x;
    if (i < N) g_mindu[i] = 0xFF800000u;   // encf(+inf)
}

// ---------------- fp32 -> fp16 conversion ----------------
__global__ void f32tof16_kernel(const float* __restrict__ src,
                                __half* __restrict__ dst, int n4) {
    int i = blockIdx.x * blockDim.x + threadIdx.x;
    if (i >= n4) return;
    float4 v = ((const float4*)src)[i];
    __half2* d = (__half2*)dst + 2 * i;
    d[0] = __floats2half2_rn(v.x, v.y);
    d[1] = __floats2half2_rn(v.z, v.w);
}

// ---------------- tensor-core helpers ----------------
__device__ __forceinline__ unsigned smaddr(const void* p) {
    unsigned r;
    asm("{.reg .u64 t; cvta.to.shared.u64 t, %1; cvt.u32.u64 %0, t;}"
        : "=r"(r) : "l"(p));
    return r;
}

__device__ __forceinline__ void ldsm4(unsigned& r0, unsigned& r1, unsigned& r2,
                                      unsigned& r3, unsigned a) {
    asm volatile("ldmatrix.sync.aligned.m8n8.x4.shared.b16 {%0,%1,%2,%3},[%4];"
                 : "=r"(r0), "=r"(r1), "=r"(r2), "=r"(r3) : "r"(a));
}

__device__ __forceinline__ void mma_f16(float* c, const unsigned* a,
                                        unsigned b0, unsigned b1) {
    asm volatile(
        "mma.sync.aligned.m16n8k16.row.col.f32.f16.f16.f32 "
        "{%0,%1,%2,%3},{%4,%5,%6,%7},{%8,%9},{%0,%1,%2,%3};"
        : "+f"(c[0]), "+f"(c[1]), "+f"(c[2]), "+f"(c[3])
        : "r"(a[0]), "r"(a[1]), "r"(a[2]), "r"(a[3]), "r"(b0), "r"(b1));
}

// ---------------- fp16 tensor-core GEMM (NT) --------------------------------
// C[i,j] = sum_k A[i,k]*B[j,k], A/B fp16, C fp32. mode 0: plain,
// 1: bias+sigmoid (+optional fp16 copy to Ch, which must NOT alias A/B),
// 2: symmetric Gram (triangular grid, mirrored store, fused prefix-min).
__global__ void __launch_bounds__(256, 2)
gemm_f16_kernel(const __half* __restrict__ A, const __half* __restrict__ B,
                float* __restrict__ C, int M, int N, int K,
                const float* __restrict__ bias, __half* __restrict__ Ch,
                int mode) {
    extern __shared__ char sm[];
    const int tid = threadIdx.x, wid = tid >> 5, lane = tid & 31;

    int bi, bj;
    if (mode == 2) {
        int id = blockIdx.x;
        bi = (int)((sqrtf(8.0f * (float)id + 1.0f) - 1.0f) * 0.5f);
        while ((bi + 1) * (bi + 2) / 2 <= id) bi++;
        while (bi * (bi + 1) / 2 > id) bi--;
        bj = id - bi * (bi + 1) / 2;
    } else {
        bi = blockIdx.y; bj = blockIdx.x;
    }
    const int rowBase = bi << 7, colBase = bj << 7;

    const int r = tid >> 1;
    const int hh = tid & 1;
    const __half* Ag = A + (size_t)(rowBase + r) * K + hh * 32;
    const __half* Bg = B + (size_t)(colBase + r) * K + hh * 32;
    unsigned stsOff[4];
#pragma unroll
    for (int j = 0; j < 4; j++)
        stsOff[j] = (unsigned)(r * 128 + ((((hh << 2) + j) ^ (r & 7)) << 4));

    const int wm = (wid & 3) << 5, wn = (wid >> 2) << 6;
    const int aRow = wm + ((lane >> 3) & 1) * 8 + (lane & 7);
    const int aQ = lane >> 4;
    const int bRow = wn + (lane >> 4) * 8 + (lane & 7);
    const int bQ = (lane >> 3) & 1;

    const unsigned smBase = smaddr(sm);

    float acc[2][8][4];
#pragma unroll
    for (int fm = 0; fm < 2; fm++)
#pragma unroll
        for (int fn = 0; fn < 8; fn++)
#pragma unroll
            for (int q = 0; q < 4; q++) acc[fm][fn][q] = 0.0f;

    uint4 la[4], lb[4];
#pragma unroll
    for (int j = 0; j < 4; j++) {
        la[j] = *(const uint4*)(Ag + j * 8);
        lb[j] = *(const uint4*)(Bg + j * 8);
    }
#pragma unroll
    for (int j = 0; j < 4; j++) {
        *(uint4*)(sm + stsOff[j]) = la[j];
        *(uint4*)(sm + 16384 + stsOff[j]) = lb[j];
    }
    __syncthreads();

    const int nt = K >> 6;
    int buf = 0;
    for (int t = 0; t < nt; t++) {
        if (t + 1 < nt) {
#pragma unroll
            for (int j = 0; j < 4; j++) {
                la[j] = *(const uint4*)(Ag + (size_t)(t + 1) * 64 + j * 8);
                lb[j] = *(const uint4*)(Bg + (size_t)(t + 1) * 64 + j * 8);
            }
        }
        const unsigned aT = smBase + buf * 32768;
        const unsigned bT = aT + 16384;
#pragma unroll
        for (int kg = 0; kg < 4; kg++) {
            unsigned afr[2][4];
#pragma unroll
            for (int fm = 0; fm < 2; fm++) {
                int rr = aRow + fm * 16;
                unsigned ad = aT + (unsigned)(rr * 128 +
                               ((((kg << 1) + aQ) ^ (rr & 7)) << 4));
                ldsm4(afr[fm][0], afr[fm][1], afr[fm][2], afr[fm][3], ad);
            }
#pragma unroll
            for (int fp = 0; fp < 4; fp++) {
                int rr = bRow + fp * 16;
                unsigned bd = bT + (unsigned)(rr * 128 +
                               ((((kg << 1) + bQ) ^ (rr & 7)) << 4));
                unsigned b00, b01, b10, b11;
                ldsm4(b00, b01, b10, b11, bd);
                mma_f16(acc[0][2 * fp],     afr[0], b00, b01);
                mma_f16(acc[0][2 * fp + 1], afr[0], b10, b11);
                mma_f16(acc[1][2 * fp],     afr[1], b00, b01);
                mma_f16(acc[1][2 * fp + 1], afr[1], b10, b11);
            }
        }
        if (t + 1 < nt) {
            buf ^= 1;
            char* dA = sm + buf * 32768;
#pragma unroll
            for (int j = 0; j < 4; j++) {
                *(uint4*)(dA + stsOff[j]) = la[j];
                *(uint4*)(dA + 16384 + stsOff[j]) = lb[j];
            }
            __syncthreads();
        }
    }

    // epilogue: c0,c1 at (row, 2c..2c+1), c2,c3 at (row+8, same cols)
    const int crow = lane >> 2;
    const int ccol = (lane & 3) * 2;
    if (mode == 1) {
#pragma unroll
        for (int fm = 0; fm < 2; fm++) {
            int rr = rowBase + wm + fm * 16 + crow;
#pragma unroll
            for (int fn = 0; fn < 8; fn++) {
                int cc = colBase + wn + fn * 8 + ccol;
                float b0v = bias[cc], b1v = bias[cc + 1];
                float2 v0, v1;
                v0.x = 1.0f / (1.0f + expf(-(acc[fm][fn][0] + b0v)));
                v0.y = 1.0f / (1.0f + expf(-(acc[fm][fn][1] + b1v)));
                v1.x = 1.0f / (1.0f + expf(-(acc[fm][fn][2] + b0v)));
                v1.y = 1.0f / (1.0f + expf(-(acc[fm][fn][3] + b1v)));
                *(float2*)&C[(size_t)rr * N + cc] = v0;
                *(float2*)&C[(size_t)(rr + 8) * N + cc] = v1;
                if (Ch) {
                    *(__half2*)&Ch[(size_t)rr * N + cc] = __floats2half2_rn(v0.x, v0.y);
                    *(__half2*)&Ch[(size_t)(rr + 8) * N + cc] = __floats2half2_rn(v1.x, v1.y);
                }
            }
        }
    } else {
#pragma unroll
        for (int fm = 0; fm < 2; fm++) {
            int rr = rowBase + wm + fm * 16 + crow;
#pragma unroll
            for (int fn = 0; fn < 8; fn++) {
                int cc = colBase + wn + fn * 8 + ccol;
                float2 v0 = make_float2(acc[fm][fn][0], acc[fm][fn][1]);
                float2 v1 = make_float2(acc[fm][fn][2], acc[fm][fn][3]);
                *(float2*)&C[(size_t)rr * N + cc] = v0;
                *(float2*)&C[(size_t)(rr + 8) * N + cc] = v1;
            }
        }
        if (mode == 2) {
            if (bi != bj) {
#pragma unroll
                for (int fm = 0; fm < 2; fm++) {
                    int rr = rowBase + wm + fm * 16 + crow;
#pragma unroll
                    for (int fn = 0; fn < 8; fn++) {
                        int cc = colBase + wn + fn * 8 + ccol;
                        C[(size_t)cc * N + rr]           = acc[fm][fn][0];
                        C[(size_t)(cc + 1) * N + rr]     = acc[fm][fn][1];
                        C[(size_t)cc * N + rr + 8]       = acc[fm][fn][2];
                        C[(size_t)(cc + 1) * N + rr + 8] = acc[fm][fn][3];
                    }
                }
            }
            // fused prefix-min: d = SEN[i] + SEN[j] - 2*G[i,j] over j<i
            float senC[8][2];
#pragma unroll
            for (int fn = 0; fn < 8; fn++) {
                senC[fn][0] = g_SEN[colBase + wn + fn * 8 + ccol];
                senC[fn][1] = g_SEN[colBase + wn + fn * 8 + ccol + 1];
            }
            float rmin[2][2] = {{INFINITY, INFINITY}, {INFINITY, INFINITY}};
#pragma unroll
            for (int fm = 0; fm < 2; fm++) {
#pragma unroll
                for (int h = 0; h < 2; h++) {
                    int lrow = wm + fm * 16 + crow + h * 8;
                    float senR = g_SEN[rowBase + lrow];
#pragma unroll
                    for (int fn = 0; fn < 8; fn++) {
#pragma unroll
                        for (int c = 0; c < 2; c++) {
                            int lcol = wn + fn * 8 + ccol + c;
                            bool ok = (bi != bj) || (lcol < lrow);
                            if (ok) {
                                float d = senR + senC[fn][c]
                                        - 2.0f * acc[fm][fn][h * 2 + c];
                                rmin[fm][h] = fminf(rmin[fm][h], d);
                            }
                        }
                    }
                }
            }
#pragma unroll
            for (int o = 1; o < 4; o <<= 1) {
#pragma unroll
                for (int fm = 0; fm < 2; fm++)
#pragma unroll
                    for (int h = 0; h < 2; h++)
                        rmin[fm][h] = fminf(rmin[fm][h],
                            __shfl_xor_sync(0xffffffffu, rmin[fm][h], o));
            }
            if ((lane & 3) == 0) {
#pragma unroll
                for (int fm = 0; fm < 2; fm++)
#pragma unroll
                    for (int h = 0; h < 2; h++) {
                        if (rmin[fm][h] < INFINITY) {
                            int gr = rowBase + wm + fm * 16 + crow + h * 8;
                            atomicMin(&g_mindu[gr], encf(rmin[fm][h]));
                        }
                    }
            }
        }
    }
}

// ---------------- sequential rule-creation scan (1 warp, ballot fast path) --
__global__ void scan_kernel(int N) {
    const int lane = threadIdx.x;
    const float DELTA = 0.13533528323661270f;  // exp(-2)
    float stau = g_base[1];
    bool st_ok = (stau > 0.0f) && (stau < 3.0e38f);
    int count = 0;

    for (int i0 = 0; i0 < N; i0 += 32) {
        int lim = (N - i0 < 32) ? (N - i0) : 32;
        int myi = i0 + lane;
        bool cert = false;
        if (myi < N && st_ok) {
            float mind = decf(g_mindu[myi]);
            cert = (expf(-mind / stau) < DELTA);
        }
        unsigned mask = __ballot_sync(0xffffffffu, cert);
        unsigned need = (lim == 32) ? 0xffffffffu : ((1u << lim) - 1u);
        if ((mask & need) == need) {
            if (lane < lim) {
                g_rules[myi] = count + lane;
                g_protos[count + lane] = myi;
            }
            count += lim;
            continue;
        }
        for (int t = 0; t < lim; t++) {
            int i = i0 + t;
            bool newr;
            int slot = 0;
            if (count == 0 || ((mask >> t) & 1u)) {
                newr = true;
            } else {
                float si = g_SEN[i];
                const float* Gi = g_G + (size_t)i * N;
                float best = -INFINITY;
                int bestr = 0x7fffffff;
                for (int rr = lane; rr < count; rr += 32) {
                    int pr = g_protos[rr];
                    float dd = si + g_SEN[pr] - 2.0f * Gi[pr];
                    float dens = expf(-dd / stau);
                    if (dens > best) { best = dens; bestr = rr; }
                }
#pragma unroll
                for (int off = 16; off; off >>= 1) {
                    float ob = __shfl_down_sync(0xffffffffu, best, off);
                    int obr = __shfl_down_sync(0xffffffffu, bestr, off);
                    if (ob > best || (ob == best && obr < bestr)) { best = ob; bestr = obr; }
                }
                best  = __shfl_sync(0xffffffffu, best, 0);
                bestr = __shfl_sync(0xffffffffu, bestr, 0);
                newr = (best < DELTA);
                slot = bestr;
            }
            if (newr) slot = count;
            if (lane == 0) g_rules[i] = slot;
            if (newr) {
                if (lane == 0) g_protos[count] = i;
                count++;
            }
        }
    }
    if (lane == 0) g_count[0] = count;
}

// ---------------- final normalized densities ----------------
__global__ void lamb_kernel(int N, float* __restrict__ out) {
    int n = blockIdx.x;
    int count = g_count[0];
    float stau = g_base[1];
    float sn = g_SEN[n];
    const float* Gn = g_G + (size_t)n * N;
    float s = 0.0f;
    for (int r = threadIdx.x; r < count; r += blockDim.x) {
        int pr = g_protos[r];
        float d = sn + g_SEN[pr] - 2.0f * Gn[pr];
        s += expf(-d / stau);
    }
    s = blockReduceSum(s);
    if (threadIdx.x == 0) {
        int pr = g_protos[g_rules[n]];
        float d = sn + g_SEN[pr] - 2.0f * Gn[pr];
        out[n] = expf(-d / stau) / s;
    }
}

// ---------------- host-side orchestration ----------------
static void convert_f16(const float* src, __half* dst, size_t n) {
    int n4 = (int)(n >> 2);
    f32tof16_kernel<<<(n4 + 255) / 256, 256>>>(src, dst, n4);
}

static void run_codebook(const __half* Xh, const float* X, int N, int K,
                         float* lamb_out, float* Gptr) {
    rowsumsq_kernel<<<N, 256>>>(X, K);
    dim3 cg((K + 255) / 256, NCHUNK);
    colsum_kernel<<<cg, 256>>>(X, N, K);
    base_kernel<<<1, 1024>>>(N, K);
    mindinit_kernel<<<(N + 255) / 256, 256>>>(N);
    int G = N / 128;
    int tri = G * (G + 1) / 2;
    gemm_f16_kernel<<<tri, 256, GEMM_SMEM>>>(Xh, Xh, Gptr, N, N, K,
                                             nullptr, nullptr, 2);
    scan_kernel<<<1, 32>>>(N);
    lamb_kernel<<<N, 256>>>(N, lamb_out);
}

extern "C" void kernel_launch(void* const* d_in, const int* in_sizes, int n_in,
                              void* d_out, int out_size) {
    const float* x  = (const float*)d_in[0];
    const float* W0 = (const float*)d_in[1];
    const float* b0 = (const float*)d_in[2];
    const float* W1 = (const float*)d_in[3];
    const float* b1 = (const float*)d_in[4];

    int DH   = in_sizes[2];            // 2048
    int DOUT = in_sizes[4];            // 1024
    int DIN  = in_sizes[1] / DH;       // 2048
    int N    = in_sizes[0] / DIN;      // 2048

    float* out   = (float*)d_out;
    float* outH  = out;                          // h: [N, DOUT]
    float* lamb0 = out + (size_t)N * DOUT;       // lambs[0]
    float* lamb1 = lamb0 + N;                    // lambs[1]

    float* Gptr = nullptr;
    float* Hptr = nullptr;
    __half* Ah = nullptr;
    __half* Bh = nullptr;
    __half* Hh = nullptr;
    cudaGetSymbolAddress((void**)&Gptr, g_G);
    cudaGetSymbolAddress((void**)&Hptr, g_H);
    cudaGetSymbolAddress((void**)&Ah, g_Ah);
    cudaGetSymbolAddress((void**)&Bh, g_Bh);
    cudaGetSymbolAddress((void**)&Hh, g_Hh);

    cudaFuncSetAttribute(gemm_f16_kernel,
                         cudaFuncAttributeMaxDynamicSharedMemorySize, GEMM_SMEM);

    // ---- layer 0 ----
    convert_f16(x, Ah, (size_t)N * DIN);
    run_codebook(Ah, x, N, DIN, lamb0, Gptr);
    convert_f16(W0, Bh, (size_t)DH * DIN);
    {
        dim3 g0(DH / 128, N / 128);
        // writes f32 H (g_H) and fp16 H (g_Hh — distinct from operands)
        gemm_f16_kernel<<<g0, 256, GEMM_SMEM>>>(Ah, Bh, Hptr, N, DH, DIN,
                                                b0, Hh, 1);
    }

    // ---- layer 1 ----
    run_codebook(Hh, Hptr, N, DH, lamb1, Gptr);
    convert_f16(W1, Bh, (size_t)DOUT * DH);
    {
        dim3 g1(DOUT / 128, N / 128);
        gemm_f16_kernel<<<g1, 256, GEMM_SMEM>>>(Hh, Bh, outH, N, DOUT, DH,
                                                b1, nullptr, 1);
    }
}

// round 9
// speedup vs baseline: 1.8443x; 1.1792x over previous
#include <cuda_runtime.h>
#include <cuda_fp16.h>
#include <math.h>
#include <stdint.h>

// SOMFNN: two layers of (ALMMo codebook lamb) + sigmoid(Linear)
// stau = base/2 (scalar); prototypes are input samples -> all distances from
// Gram = X X^T; min-distance-over-all-predecessors shortcut for new rules.
// GEMMs: fp16 mma.sync.m16n8k16 (fp32 accum), SW128-swizzled smem.
// This round: role-split merged launches (gram || lin in one MEGA kernel,
// aux roles batched) to kill launch-serialization; 8 launches total.

#define MAXN 2048
#define MAXD 2048
#define NCHUNK 32
#define NCONV 512
#define GEMM_SMEM 65536

__device__ float g_G0[(size_t)MAXN * MAXN];
__device__ float g_G1[(size_t)MAXN * MAXN];
__device__ float g_H[(size_t)MAXN * MAXD];
__device__ __half g_Ah[(size_t)MAXN * MAXD];
__device__ __half g_Bh[(size_t)MAXN * MAXD];
__device__ __half g_Hh[(size_t)MAXN * MAXD];
__device__ float g_SEN[2][MAXN];
__device__ float g_colpart[NCHUNK][MAXD];
__device__ float g_base[2][2];
__device__ unsigned g_mindu[2][MAXN];
__device__ int   g_rules[2][MAXN];
__device__ int   g_protos[2][MAXN];
__device__ int   g_count[2];

// order-preserving float<->unsigned encoding (monotone; min exact)
__device__ __forceinline__ unsigned encf(float f) {
    unsigned u = __float_as_uint(f);
    return (u & 0x80000000u) ? ~u : (u | 0x80000000u);
}
__device__ __forceinline__ float decf(unsigned e) {
    unsigned u = (e & 0x80000000u) ? (e ^ 0x80000000u) : ~e;
    return __uint_as_float(u);
}

__device__ __forceinline__ float blockReduceSum(float v) {
    __shared__ float sh[32];
    int lane = threadIdx.x & 31, wid = threadIdx.x >> 5;
#pragma unroll
    for (int o = 16; o; o >>= 1) v += __shfl_down_sync(0xffffffffu, v, o);
    __syncthreads();
    if (lane == 0) sh[wid] = v;
    __syncthreads();
    if (wid == 0) {
        int nw = (blockDim.x + 31) >> 5;
        v = (lane < nw) ? sh[lane] : 0.0f;
#pragma unroll
        for (int o = 16; o; o >>= 1) v += __shfl_down_sync(0xffffffffu, v, o);
    }
    return v;
}

// ---------------- sequential rule-creation scan (device fn, 1 warp) --------
__device__ void scan_dev(const float* G, const float* sen,
                         const unsigned* mindu, const float* base,
                         int* rules, int* protos, int* count, int N) {
    const int lane = threadIdx.x & 31;
    const float DELTA = 0.13533528323661270f;  // exp(-2)
    float stau = base[1];
    bool st_ok = (stau > 0.0f) && (stau < 3.0e38f);
    int cnt = 0;

    for (int i0 = 0; i0 < N; i0 += 32) {
        int lim = (N - i0 < 32) ? (N - i0) : 32;
        int myi = i0 + lane;
        bool cert = false;
        if (myi < N && st_ok) {
            float mind = decf(mindu[myi]);
            cert = (expf(-mind / stau) < DELTA);
        }
        unsigned mask = __ballot_sync(0xffffffffu, cert);
        unsigned need = (lim == 32) ? 0xffffffffu : ((1u << lim) - 1u);
        if ((mask & need) == need) {
            if (lane < lim) {
                rules[myi] = cnt + lane;
                protos[cnt + lane] = myi;
            }
            cnt += lim;
            continue;
        }
        for (int t = 0; t < lim; t++) {
            int i = i0 + t;
            bool newr;
            int slot = 0;
            if (cnt == 0 || ((mask >> t) & 1u)) {
                newr = true;
            } else {
                float si = sen[i];
                const float* Gi = G + (size_t)i * N;
                float best = -INFINITY;
                int bestr = 0x7fffffff;
                for (int rr = lane; rr < cnt; rr += 32) {
                    int pr = protos[rr];
                    float dd = si + sen[pr] - 2.0f * Gi[pr];
                    float dens = expf(-dd / stau);
                    if (dens > best) { best = dens; bestr = rr; }
                }
#pragma unroll
                for (int off = 16; off; off >>= 1) {
                    float ob = __shfl_down_sync(0xffffffffu, best, off);
                    int obr = __shfl_down_sync(0xffffffffu, bestr, off);
                    if (ob > best || (ob == best && obr < bestr)) { best = ob; bestr = obr; }
                }
                best  = __shfl_sync(0xffffffffu, best, 0);
                bestr = __shfl_sync(0xffffffffu, bestr, 0);
                newr = (best < DELTA);
                slot = bestr;
            }
            if (newr) slot = cnt;
            if (lane == 0) rules[i] = slot;
            if (newr) {
                if (lane == 0) protos[cnt] = i;
                cnt++;
            }
        }
    }
    if (lane == 0) count[0] = cnt;
}

// ---------------- fused aux kernel (role-split grid) -------------------------
// roles: [convert X f32->f16] [convert W f32->f16] [rowsumsq X] [colsum X]
//        [optional scan of previous layer]
__global__ void fused_aux_kernel(
    const float* __restrict__ X, __half* __restrict__ Xh, int N, int K,
    const float* __restrict__ W, __half* __restrict__ Wh, int WM,
    float* __restrict__ sen,
    const float* Gprev, const float* senPrev, const unsigned* minduPrev,
    const float* basePrev, int* rulesPrev, int* protosPrev, int* countPrev,
    int Nprev)
{
    int bid = blockIdx.x;
    const int tid = threadIdx.x;

    const int nConvX = Xh ? NCONV : 0;
    if (bid < nConvX) {
        int n4 = (N * K) >> 2;
        for (int i = bid * 256 + tid; i < n4; i += nConvX * 256) {
            float4 v = ((const float4*)X)[i];
            __half2* d = (__half2*)Xh + 2 * i;
            d[0] = __floats2half2_rn(v.x, v.y);
            d[1] = __floats2half2_rn(v.z, v.w);
        }
        return;
    }
    bid -= nConvX;

    const int nConvW = Wh ? NCONV : 0;
    if (bid < nConvW) {
        int n4 = (WM * K) >> 2;
        for (int i = bid * 256 + tid; i < n4; i += nConvW * 256) {
            float4 v = ((const float4*)W)[i];
            __half2* d = (__half2*)Wh + 2 * i;
            d[0] = __floats2half2_rn(v.x, v.y);
            d[1] = __floats2half2_rn(v.z, v.w);
        }
        return;
    }
    bid -= nConvW;

    if (bid < N) {   // rowsumsq: one block per row
        const float4* row = (const float4*)(X + (size_t)bid * K);
        float s = 0.0f;
        for (int k = tid; k < (K >> 2); k += 256) {
            float4 v = row[k];
            s += v.x * v.x + v.y * v.y + v.z * v.z + v.w * v.w;
        }
        s = blockReduceSum(s);
        if (tid == 0) sen[bid] = s;
        return;
    }
    bid -= N;

    const int nCol = (K >> 8) * NCHUNK;
    if (bid < nCol) {   // colsum chunks
        int chunk = bid / (K >> 8);
        int cseg = bid % (K >> 8);
        int c = cseg * 256 + tid;
        int r0 = chunk * (N / NCHUNK), r1 = r0 + N / NCHUNK;
        float s = 0.0f;
        for (int i = r0; i < r1; i++) s += X[(size_t)i * K + c];
        g_colpart[chunk][c] = s;
        return;
    }
    bid -= nCol;

    if (Gprev && bid == 0 && tid < 32)
        scan_dev(Gprev, senPrev, minduPrev, basePrev,
                 rulesPrev, protosPrev, countPrev, Nprev);
}

// ---------------- base + mindinit (single block, 1024 threads) -------------
__global__ void base_mind_kernel(const float* __restrict__ sen,
                                 unsigned* __restrict__ mindu,
                                 float* __restrict__ baseout, int N, int K) {
    float invN = 1.0f / (float)N;
    float s1 = 0.0f, s2 = 0.0f;
    for (int i = threadIdx.x; i < N; i += blockDim.x) s1 += sen[i];
    for (int c = threadIdx.x; c < K; c += blockDim.x) {
        float cs = 0.0f;
#pragma unroll
        for (int h = 0; h < NCHUNK; h++) cs += g_colpart[h][c];
        float m = cs * invN;
        s2 += m * m;
    }
    s1 = blockReduceSum(s1);
    __syncthreads();
    s2 = blockReduceSum(s2);
    if (threadIdx.x == 0) {
        float base = s1 * invN - s2;
        baseout[0] = base;
        baseout[1] = 0.5f * base;
    }
    for (int i = threadIdx.x; i < N; i += blockDim.x)
        mindu[i] = 0xFF800000u;   // encf(+inf)
}

// ---------------- tensor-core helpers ----------------
__device__ __forceinline__ unsigned smaddr(const void* p) {
    unsigned r;
    asm("{.reg .u64 t; cvta.to.shared.u64 t, %1; cvt.u32.u64 %0, t;}"
        : "=r"(r) : "l"(p));
    return r;
}

__device__ __forceinline__ void ldsm4(unsigned& r0, unsigned& r1, unsigned& r2,
                                      unsigned& r3, unsigned a) {
    asm volatile("ldmatrix.sync.aligned.m8n8.x4.shared.b16 {%0,%1,%2,%3},[%4];"
                 : "=r"(r0), "=r"(r1), "=r"(r2), "=r"(r3) : "r"(a));
}

__device__ __forceinline__ void mma_f16(float* c, const unsigned* a,
                                        unsigned b0, unsigned b1) {
    asm volatile(
        "mma.sync.aligned.m16n8k16.row.col.f32.f16.f16.f32 "
        "{%0,%1,%2,%3},{%4,%5,%6,%7},{%8,%9},{%0,%1,%2,%3};"
        : "+f"(c[0]), "+f"(c[1]), "+f"(c[2]), "+f"(c[3])
        : "r"(a[0]), "r"(a[1]), "r"(a[2]), "r"(a[3]), "r"(b0), "r"(b1));
}

// ---------------- MEGA GEMM: gram (mode2) || linear (mode1) in one grid ----
// gram: C=G (Ng x Ng), A=B=Agr, K=Kg, fused prefix-min into mindu.
// lin:  C=Cl (Ml x Nl), A=Al, B=Bl, K=Kl, bias+sigmoid (+fp16 copy to Chl).
__global__ void __launch_bounds__(256, 2)
mega_gemm_kernel(const __half* __restrict__ Agr, float* __restrict__ G,
                 int Ng, int Kg, const float* __restrict__ sen,
                 unsigned* __restrict__ mindu, int triCount,
                 const __half* __restrict__ Al, const __half* __restrict__ Bl,
                 float* __restrict__ Cl, __half* __restrict__ Chl,
                 const float* __restrict__ bias, int Nl, int Kl) {
    extern __shared__ char sm[];
    const int tid = threadIdx.x, wid = tid >> 5, lane = tid & 31;

    const __half *A, *B;
    float* C;
    __half* Ch;
    int NC, K, mode, bi, bj;
    if ((int)blockIdx.x < triCount) {
        int id = blockIdx.x;
        bi = (int)((sqrtf(8.0f * (float)id + 1.0f) - 1.0f) * 0.5f);
        while ((bi + 1) * (bi + 2) / 2 <= id) bi++;
        while (bi * (bi + 1) / 2 > id) bi--;
        bj = id - bi * (bi + 1) / 2;
        A = Agr; B = Agr; C = G; Ch = nullptr; NC = Ng; K = Kg; mode = 2;
    } else {
        int lid = blockIdx.x - triCount;
        int nbx = Nl >> 7;
        bi = lid / nbx; bj = lid % nbx;
        A = Al; B = Bl; C = Cl; Ch = Chl; NC = Nl; K = Kl; mode = 1;
    }
    const int rowBase = bi << 7, colBase = bj << 7;

    const int r = tid >> 1;
    const int hh = tid & 1;
    const __half* Ag = A + (size_t)(rowBase + r) * K + hh * 32;
    const __half* Bg = B + (size_t)(colBase + r) * K + hh * 32;
    unsigned stsOff[4];
#pragma unroll
    for (int j = 0; j < 4; j++)
        stsOff[j] = (unsigned)(r * 128 + ((((hh << 2) + j) ^ (r & 7)) << 4));

    const int wm = (wid & 3) << 5, wn = (wid >> 2) << 6;
    const int aRow = wm + ((lane >> 3) & 1) * 8 + (lane & 7);
    const int aQ = lane >> 4;
    const int bRow = wn + (lane >> 4) * 8 + (lane & 7);
    const int bQ = (lane >> 3) & 1;

    const unsigned smBase = smaddr(sm);

    float acc[2][8][4];
#pragma unroll
    for (int fm = 0; fm < 2; fm++)
#pragma unroll
        for (int fn = 0; fn < 8; fn++)
#pragma unroll
            for (int q = 0; q < 4; q++) acc[fm][fn][q] = 0.0f;

    uint4 la[4], lb[4];
#pragma unroll
    for (int j = 0; j < 4; j++) {
        la[j] = *(const uint4*)(Ag + j * 8);
        lb[j] = *(const uint4*)(Bg + j * 8);
    }
#pragma unroll
    for (int j = 0; j < 4; j++) {
        *(uint4*)(sm + stsOff[j]) = la[j];
        *(uint4*)(sm + 16384 + stsOff[j]) = lb[j];
    }
    __syncthreads();

    const int nt = K >> 6;
    int buf = 0;
    for (int t = 0; t < nt; t++) {
        if (t + 1 < nt) {
#pragma unroll
            for (int j = 0; j < 4; j++) {
                la[j] = *(const uint4*)(Ag + (size_t)(t + 1) * 64 + j * 8);
                lb[j] = *(const uint4*)(Bg + (size_t)(t + 1) * 64 + j * 8);
            }
        }
        const unsigned aT = smBase + buf * 32768;
        const unsigned bT = aT + 16384;
#pragma unroll
        for (int kg = 0; kg < 4; kg++) {
            unsigned afr[2][4];
#pragma unroll
            for (int fm = 0; fm < 2; fm++) {
                int rr = aRow + fm * 16;
                unsigned ad = aT + (unsigned)(rr * 128 +
                               ((((kg << 1) + aQ) ^ (rr & 7)) << 4));
                ldsm4(afr[fm][0], afr[fm][1], afr[fm][2], afr[fm][3], ad);
            }
#pragma unroll
            for (int fp = 0; fp < 4; fp++) {
                int rr = bRow + fp * 16;
                unsigned bd = bT + (unsigned)(rr * 128 +
                               ((((kg << 1) + bQ) ^ (rr & 7)) << 4));
                unsigned b00, b01, b10, b11;
                ldsm4(b00, b01, b10, b11, bd);
                mma_f16(acc[0][2 * fp],     afr[0], b00, b01);
                mma_f16(acc[0][2 * fp + 1], afr[0], b10, b11);
                mma_f16(acc[1][2 * fp],     afr[1], b00, b01);
                mma_f16(acc[1][2 * fp + 1], afr[1], b10, b11);
            }
        }
        if (t + 1 < nt) {
            buf ^= 1;
            char* dA = sm + buf * 32768;
#pragma unroll
            for (int j = 0; j < 4; j++) {
                *(uint4*)(dA + stsOff[j]) = la[j];
                *(uint4*)(dA + 16384 + stsOff[j]) = lb[j];
            }
            __syncthreads();
        }
    }

    const int crow = lane >> 2;
    const int ccol = (lane & 3) * 2;
    if (mode == 1) {
#pragma unroll
        for (int fm = 0; fm < 2; fm++) {
            int rr = rowBase + wm + fm * 16 + crow;
#pragma unroll
            for (int fn = 0; fn < 8; fn++) {
                int cc = colBase + wn + fn * 8 + ccol;
                float b0v = bias[cc], b1v = bias[cc + 1];
                float2 v0, v1;
                v0.x = 1.0f / (1.0f + expf(-(acc[fm][fn][0] + b0v)));
                v0.y = 1.0f / (1.0f + expf(-(acc[fm][fn][1] + b1v)));
                v1.x = 1.0f / (1.0f + expf(-(acc[fm][fn][2] + b0v)));
                v1.y = 1.0f / (1.0f + expf(-(acc[fm][fn][3] + b1v)));
                *(float2*)&C[(size_t)rr * NC + cc] = v0;
                *(float2*)&C[(size_t)(rr + 8) * NC + cc] = v1;
                if (Ch) {
                    *(__half2*)&Ch[(size_t)rr * NC + cc] = __floats2half2_rn(v0.x, v0.y);
                    *(__half2*)&Ch[(size_t)(rr + 8) * NC + cc] = __floats2half2_rn(v1.x, v1.y);
                }
            }
        }
    } else {
#pragma unroll
        for (int fm = 0; fm < 2; fm++) {
            int rr = rowBase + wm + fm * 16 + crow;
#pragma unroll
            for (int fn = 0; fn < 8; fn++) {
                int cc = colBase + wn + fn * 8 + ccol;
                float2 v0 = make_float2(acc[fm][fn][0], acc[fm][fn][1]);
                float2 v1 = make_float2(acc[fm][fn][2], acc[fm][fn][3]);
                *(float2*)&C[(size_t)rr * NC + cc] = v0;
                *(float2*)&C[(size_t)(rr + 8) * NC + cc] = v1;
            }
        }
        if (bi != bj) {
#pragma unroll
            for (int fm = 0; fm < 2; fm++) {
                int rr = rowBase + wm + fm * 16 + crow;
#pragma unroll
                for (int fn = 0; fn < 8; fn++) {
                    int cc = colBase + wn + fn * 8 + ccol;
                    C[(size_t)cc * NC + rr]           = acc[fm][fn][0];
                    C[(size_t)(cc + 1) * NC + rr]     = acc[fm][fn][1];
                    C[(size_t)cc * NC + rr + 8]       = acc[fm][fn][2];
                    C[(size_t)(cc + 1) * NC + rr + 8] = acc[fm][fn][3];
                }
            }
        }
        // fused prefix-min: d = SEN[i] + SEN[j] - 2*G[i,j] over j<i
        float senC[8][2];
#pragma unroll
        for (int fn = 0; fn < 8; fn++) {
            senC[fn][0] = sen[colBase + wn + fn * 8 + ccol];
            senC[fn][1] = sen[colBase + wn + fn * 8 + ccol + 1];
        }
        float rmin[2][2] = {{INFINITY, INFINITY}, {INFINITY, INFINITY}};
#pragma unroll
        for (int fm = 0; fm < 2; fm++) {
#pragma unroll
            for (int h = 0; h < 2; h++) {
                int lrow = wm + fm * 16 + crow + h * 8;
                float senR = sen[rowBase + lrow];
#pragma unroll
                for (int fn = 0; fn < 8; fn++) {
#pragma unroll
                    for (int c = 0; c < 2; c++) {
                        int lcol = wn + fn * 8 + ccol + c;
                        bool ok = (bi != bj) || (lcol < lrow);
                        if (ok) {
                            float d = senR + senC[fn][c]
                                    - 2.0f * acc[fm][fn][h * 2 + c];
                            rmin[fm][h] = fminf(rmin[fm][h], d);
                        }
                    }
                }
            }
        }
#pragma unroll
        for (int o = 1; o < 4; o <<= 1) {
#pragma unroll
            for (int fm = 0; fm < 2; fm++)
#pragma unroll
                for (int h = 0; h < 2; h++)
                    rmin[fm][h] = fminf(rmin[fm][h],
                        __shfl_xor_sync(0xffffffffu, rmin[fm][h], o));
        }
        if ((lane & 3) == 0) {
#pragma unroll
            for (int fm = 0; fm < 2; fm++)
#pragma unroll
                for (int h = 0; h < 2; h++) {
                    if (rmin[fm][h] < INFINITY) {
                        int gr = rowBase + wm + fm * 16 + crow + h * 8;
                        atomicMin(&mindu[gr], encf(rmin[fm][h]));
                    }
                }
        }
    }
}

// ---------------- standalone scan (layer 1) ----------------
__global__ void scan1_kernel(const float* G, const float* sen,
                             const unsigned* mindu, const float* base,
                             int* rules, int* protos, int* count, int N) {
    if (threadIdx.x < 32)
        scan_dev(G, sen, mindu, base, rules, protos, count, N);
}

// ---------------- merged final normalized densities ----------------
__global__ void lamb2_kernel(int N, float* __restrict__ out0,
                             float* __restrict__ out1) {
    int layer = (int)blockIdx.x >= N;
    int n = blockIdx.x - layer * N;
    const float* G = layer ? g_G1 : g_G0;
    const float* sen = g_SEN[layer];
    const int* rules = g_rules[layer];
    const int* protos = g_protos[layer];
    int count = g_count[layer];
    float stau = g_base[layer][1];
    float* out = layer ? out1 : out0;

    float sn = sen[n];
    const float* Gn = G + (size_t)n * N;
    float s = 0.0f;
    for (int r = threadIdx.x; r < count; r += blockDim.x) {
        int pr = protos[r];
        float d = sn + sen[pr] - 2.0f * Gn[pr];
        s += expf(-d / stau);
    }
    s = blockReduceSum(s);
    if (threadIdx.x == 0) {
        int pr = protos[rules[n]];
        float d = sn + sen[pr] - 2.0f * Gn[pr];
        out[n] = expf(-d / stau) / s;
    }
}

// ---------------- host-side orchestration ----------------
extern "C" void kernel_launch(void* const* d_in, const int* in_sizes, int n_in,
                              void* d_out, int out_size) {
    const float* x  = (const float*)d_in[0];
    const float* W0 = (const float*)d_in[1];
    const float* b0 = (const float*)d_in[2];
    const float* W1 = (const float*)d_in[3];
    const float* b1 = (const float*)d_in[4];

    int DH   = in_sizes[2];            // 2048
    int DOUT = in_sizes[4];            // 1024
    int DIN  = in_sizes[1] / DH;       // 2048
    int N    = in_sizes[0] / DIN;      // 2048

    float* out   = (float*)d_out;
    float* outH  = out;
    float* lamb0 = out + (size_t)N * DOUT;
    float* lamb1 = lamb0 + N;

    float *G0p, *G1p, *Hp, *SENp, *basep;
    __half *Ahp, *Bhp, *Hhp;
    unsigned* mindup;
    int *rulesp, *protosp, *countp;
    cudaGetSymbolAddress((void**)&G0p, g_G0);
    cudaGetSymbolAddress((void**)&G1p, g_G1);
    cudaGetSymbolAddress((void**)&Hp, g_H);
    cudaGetSymbolAddress((void**)&Ahp, g_Ah);
    cudaGetSymbolAddress((void**)&Bhp, g_Bh);
    cudaGetSymbolAddress((void**)&Hhp, g_Hh);
    cudaGetSymbolAddress((void**)&SENp, g_SEN);
    cudaGetSymbolAddress((void**)&basep, g_base);
    cudaGetSymbolAddress((void**)&mindup, g_mindu);
    cudaGetSymbolAddress((void**)&rulesp, g_rules);
    cudaGetSymbolAddress((void**)&protosp, g_protos);
    cudaGetSymbolAddress((void**)&countp, g_count);

    float* SEN0 = SENp;            float* SEN1 = SENp + MAXN;
    float* base0 = basep;          float* base1 = basep + 2;
    unsigned* mind0 = mindup;      unsigned* mind1 = mindup + MAXN;
    int* rules0 = rulesp;          int* rules1 = rulesp + MAXN;
    int* protos0 = protosp;        int* protos1 = protosp + MAXN;
    int* count0 = countp;          int* count1 = countp + 1;

    cudaFuncSetAttribute(mega_gemm_kernel,
                         cudaFuncAttributeMaxDynamicSharedMemorySize, GEMM_SMEM);

    const int tri = (N / 128) * (N / 128 + 1) / 2;   // 136

    // 1) aux0: convert x -> Ah || convert W0 -> Bh || rowsumsq(x) || colsum(x)
    {
        int grid = NCONV + NCONV + N + (DIN >> 8) * NCHUNK;
        fused_aux_kernel<<<grid, 256>>>(x, Ahp, N, DIN, W0, Bhp, DH, SEN0,
                                        nullptr, nullptr, nullptr, nullptr,
                                        nullptr, nullptr, nullptr, 0);
    }
    // 2) base0 + mindinit0
    base_mind_kernel<<<1, 1024>>>(SEN0, mind0, base0, N, DIN);
    // 3) MEGA0: gram0 (Ah -> G0, mind0) || lin0 (Ah,Bh -> H, Hh)
    {
        int grid = tri + (N / 128) * (DH / 128);
        mega_gemm_kernel<<<grid, 256, GEMM_SMEM>>>(
            Ahp, G0p, N, DIN, SEN0, mind0, tri,
            Ahp, Bhp, Hp, Hhp, b0, DH, DIN);
    }
    // 4) aux1: scan0 || rowsumsq(H) || colsum(H) || convert W1 -> Bh
    {
        int grid = NCONV + N + (DH >> 8) * NCHUNK + 1;
        fused_aux_kernel<<<grid, 256>>>(Hp, nullptr, N, DH, W1, Bhp, DOUT, SEN1,
                                        G0p, SEN0, mind0, base0,
                                        rules0, protos0, count0, N);
    }
    // 5) base1 + mindinit1
    base_mind_kernel<<<1, 1024>>>(SEN1, mind1, base1, N, DH);
    // 6) MEGA1: gram1 (Hh -> G1, mind1) || lin1 (Hh,Bh -> outH)
    {
        int grid = tri + (N / 128) * (DOUT / 128);
        mega_gemm_kernel<<<grid, 256, GEMM_SMEM>>>(
            Hhp, G1p, N, DH, SEN1, mind1, tri,
            Hhp, Bhp, outH, nullptr, b1, DOUT, DH);
    }
    // 7) scan1
    scan1_kernel<<<1, 32>>>(G1p, SEN1, mind1, base1,
                            rules1, protos1, count1, N);
    // 8) lamb0 || lamb1
    lamb2_kernel<<<2 * N, 256>>>(N, lamb0, lamb1);
}